// round 2
// baseline (speedup 1.0000x reference)
#include <cuda_runtime.h>
#include <math.h>

// Global scratch: 10 bins x (count, sum_conf, sum_acc) as doubles + dtype flag.
__device__ double g_bins[30];
__device__ int g_label64;   // 1 => labels are int64, 0 => int32

__global__ void zero_bins_kernel() {
    int t = threadIdx.x;
    if (t < 30) g_bins[t] = 0.0;
}

// Probe label dtype: interpret first P entries as int64. If any is outside
// [0, C) the buffer must be int32 (two adjacent int32 labels combined give
// values >= 2^32 whenever the odd word is nonzero). Deterministic.
__global__ void probe_labels_kernel(const void* labels, int N, int C) {
    if (threadIdx.x == 0 && blockIdx.x == 0) {
        const long long* p = (const long long*)labels;
        int P = N / 2; if (P > 4096) P = 4096;
        int ok64 = 1;
        for (int i = 0; i < P; i++) {
            long long v = p[i];
            if (v < 0 || v >= (long long)C) { ok64 = 0; break; }
        }
        g_label64 = ok64;
    }
}

// One warp per row (grid-stride). conf = exp(max(row)); pred = argmax (first
// occurrence); bin = ceil(conf*10)-1, dropped if out of [0,10).
__global__ __launch_bounds__(256) void ece_main_kernel(
    const float* __restrict__ logits,
    const void*  __restrict__ labels,
    int N, int C)
{
    __shared__ float sb[8][30];   // per-warp private bin slices

    const int warp = threadIdx.x >> 5;
    const int lane = threadIdx.x & 31;

    if (lane < 30) sb[warp][lane] = 0.0f;
    __syncwarp();

    const int lab64 = g_label64;
    const int warpsTotal = gridDim.x * (blockDim.x >> 5);
    const int gwarp = blockIdx.x * (blockDim.x >> 5) + warp;
    const int C4 = C >> 2;
    const bool vec_ok = ((C & 3) == 0);

    for (int row = gwarp; row < N; row += warpsTotal) {
        float v = -INFINITY;
        int   idx = 0x7fffffff;

        if (vec_ok) {
            const float4* p = reinterpret_cast<const float4*>(logits + (size_t)row * C);
            for (int c = lane; c < C4; c += 32) {
                float4 x = p[c];
                int b = c << 2;
                if (x.x > v) { v = x.x; idx = b;     }
                if (x.y > v) { v = x.y; idx = b + 1; }
                if (x.z > v) { v = x.z; idx = b + 2; }
                if (x.w > v) { v = x.w; idx = b + 3; }
            }
        } else {
            const float* p = logits + (size_t)row * C;
            for (int c = lane; c < C; c += 32) {
                float x = p[c];
                if (x > v) { v = x; idx = c; }
            }
        }

        // Warp reduce: max value, min index on ties (first occurrence).
        #pragma unroll
        for (int off = 16; off; off >>= 1) {
            float ov = __shfl_down_sync(0xffffffffu, v,   off);
            int   oi = __shfl_down_sync(0xffffffffu, idx, off);
            if (ov > v || (ov == v && oi < idx)) { v = ov; idx = oi; }
        }

        if (lane == 0) {
            float conf = expf(v);
            int bin = (int)ceilf(conf * 10.0f) - 1;
            if (bin >= 0 && bin < 10) {
                int lab;
                if (lab64) lab = (int)((const long long*)labels)[row];
                else       lab = ((const int*)labels)[row];
                float acc = (idx == lab) ? 1.0f : 0.0f;
                sb[warp][bin * 3 + 0] += 1.0f;
                sb[warp][bin * 3 + 1] += conf;
                sb[warp][bin * 3 + 2] += acc;
            }
        }
    }

    __syncthreads();

    // Block reduce 8 warp slices -> 30 global double atomics.
    int t = threadIdx.x;
    if (t < 30) {
        float s = 0.0f;
        #pragma unroll
        for (int w = 0; w < 8; w++) s += sb[w][t];
        atomicAdd(&g_bins[t], (double)s);
    }
}

__global__ void ece_final_kernel(float* __restrict__ out, int N) {
    if (threadIdx.x == 0 && blockIdx.x == 0) {
        double ece = 0.0;
        double n = (double)N;
        #pragma unroll
        for (int b = 0; b < 10; b++) {
            double cnt = g_bins[b * 3 + 0];
            double sc  = g_bins[b * 3 + 1];
            double sa  = g_bins[b * 3 + 2];
            if (cnt > 0.0) {
                ece += fabs(sc / cnt - sa / cnt) * (cnt / n);
            }
        }
        out[0] = (float)ece;
    }
}

extern "C" void kernel_launch(void* const* d_in, const int* in_sizes, int n_in,
                              void* d_out, int out_size)
{
    // Identify inputs by element count: logits is the (much) larger buffer.
    int li = 0, bi = 1;
    if (in_sizes[1] > in_sizes[0]) { li = 1; bi = 0; }

    const float* logits = (const float*)d_in[li];
    const void*  labels = d_in[bi];

    int N = in_sizes[bi];             // number of rows (labels count)
    int C = in_sizes[li] / N;         // classes per row

    zero_bins_kernel<<<1, 32>>>();
    probe_labels_kernel<<<1, 32>>>(labels, N, C);

    int blocks = 2368;
    int maxBlocks = (N + 7) / 8;      // 8 warps/block, warp-per-row
    if (blocks > maxBlocks) blocks = maxBlocks;
    if (blocks < 1) blocks = 1;

    ece_main_kernel<<<blocks, 256>>>(logits, labels, N, C);
    ece_final_kernel<<<1, 32>>>((float*)d_out, N);
}

// round 3
// speedup vs baseline: 1.6340x; 1.6340x over previous
#include <cuda_runtime.h>
#include <math.h>

__device__ double g_bins[30];
__device__ int g_label64;   // 1 => labels are int64, 0 => int32

// Fused: zero bins + parallel label-dtype probe.
// Interpret first P label entries as int64; any value outside [0,C) proves
// the buffer is int32 (adjacent int32 pairs form values >= 2^32 with
// overwhelming probability for random labels). Deterministic per input.
__global__ void setup_kernel(const void* labels, int N, int C) {
    int t = threadIdx.x;
    if (t < 30) g_bins[t] = 0.0;

    const long long* p = (const long long*)labels;
    int P = N / 2; if (P > 4096) P = 4096;
    bool bad = false;
    for (int i = t; i < P; i += blockDim.x) {
        long long v = p[i];
        if (v < 0 || v >= (long long)C) bad = true;
    }
    unsigned any_bad = __ballot_sync(0xffffffffu, bad);
    __shared__ int s_bad;
    if (t == 0) s_bad = 0;
    __syncthreads();
    if ((t & 31) == 0 && any_bad) atomicOr(&s_bad, 1);
    __syncthreads();
    if (t == 0) g_label64 = s_bad ? 0 : 1;
}

__device__ __forceinline__ void warp_argmax_reduce(float& v, int& idx) {
    #pragma unroll
    for (int off = 16; off; off >>= 1) {
        float ov = __shfl_down_sync(0xffffffffu, v,   off);
        int   oi = __shfl_down_sync(0xffffffffu, idx, off);
        if (ov > v || (ov == v && oi < idx)) { v = ov; idx = oi; }
    }
}

__device__ __forceinline__ void lane_max4(float4 x, int b, float& v, int& idx) {
    if (x.x > v) { v = x.x; idx = b;     }
    if (x.y > v) { v = x.y; idx = b + 1; }
    if (x.z > v) { v = x.z; idx = b + 2; }
    if (x.w > v) { v = x.w; idx = b + 3; }
}

__device__ __forceinline__ void accum_bin(float* slice, float v, int idx,
                                          const void* labels, int row, int lab64) {
    float conf = __expf(v);
    int bin = (int)ceilf(conf * 10.0f) - 1;
    if (bin >= 0 && bin < 10) {
        int lab;
        if (lab64) lab = (int)((const long long*)labels)[row];
        else       lab = ((const int*)labels)[row];
        float acc = (idx == lab) ? 1.0f : 0.0f;
        slice[bin * 3 + 0] += 1.0f;
        slice[bin * 3 + 1] += conf;
        slice[bin * 3 + 2] += acc;
    }
}

// One warp per 4 rows per iteration. conf = exp(max(row)); pred = argmax
// (first occurrence); bin = ceil(conf*10)-1, dropped if out of [0,10).
__global__ __launch_bounds__(256) void ece_main_kernel(
    const float* __restrict__ logits,
    const void*  __restrict__ labels,
    int N, int C)
{
    __shared__ float sb[8][30];

    const int warp = threadIdx.x >> 5;
    const int lane = threadIdx.x & 31;

    if (lane < 30) sb[warp][lane] = 0.0f;
    __syncwarp();

    float* slice = sb[warp];
    const int lab64 = g_label64;
    const int warpsTotal = gridDim.x * (blockDim.x >> 5);
    const int gwarp = blockIdx.x * (blockDim.x >> 5) + warp;
    const int C4 = C >> 2;

    if ((C & 3) == 0 && C4 <= 32) {
        // Specialized: whole row covered by one float4 per lane.
        const bool act = (lane < C4);
        const int b = lane << 2;
        const int nChunks = N >> 2;          // groups of 4 rows
        const float4 NEG = make_float4(-INFINITY, -INFINITY, -INFINITY, -INFINITY);

        for (int ch = gwarp; ch < nChunks; ch += warpsTotal) {
            const int r0 = ch << 2;
            const float4* p = reinterpret_cast<const float4*>(logits + (size_t)r0 * C);
            const int s = C4;                // float4 stride per row
            // Issue all 4 loads before any reduce (MLP=4 per warp).
            float4 x0 = act ? p[lane]         : NEG;
            float4 x1 = act ? p[lane + s]     : NEG;
            float4 x2 = act ? p[lane + 2*s]   : NEG;
            float4 x3 = act ? p[lane + 3*s]   : NEG;

            float v0 = -INFINITY, v1 = -INFINITY, v2 = -INFINITY, v3 = -INFINITY;
            int i0 = 0x7fffffff, i1 = 0x7fffffff, i2 = 0x7fffffff, i3 = 0x7fffffff;
            lane_max4(x0, b, v0, i0);
            lane_max4(x1, b, v1, i1);
            lane_max4(x2, b, v2, i2);
            lane_max4(x3, b, v3, i3);

            warp_argmax_reduce(v0, i0);
            warp_argmax_reduce(v1, i1);
            warp_argmax_reduce(v2, i2);
            warp_argmax_reduce(v3, i3);

            if (lane == 0) {
                accum_bin(slice, v0, i0, labels, r0 + 0, lab64);
                accum_bin(slice, v1, i1, labels, r0 + 1, lab64);
                accum_bin(slice, v2, i2, labels, r0 + 2, lab64);
                accum_bin(slice, v3, i3, labels, r0 + 3, lab64);
            }
        }

        // Tail rows (N % 4), handled by first warps.
        for (int row = (nChunks << 2) + gwarp; row < N; row += warpsTotal) {
            const float4* p = reinterpret_cast<const float4*>(logits + (size_t)row * C);
            float v = -INFINITY; int idx = 0x7fffffff;
            if (act) { float4 x = p[lane]; lane_max4(x, b, v, idx); }
            warp_argmax_reduce(v, idx);
            if (lane == 0) accum_bin(slice, v, idx, labels, row, lab64);
        }
    } else {
        // Generic fallback.
        for (int row = gwarp; row < N; row += warpsTotal) {
            float v = -INFINITY; int idx = 0x7fffffff;
            const float* p = logits + (size_t)row * C;
            for (int c = lane; c < C; c += 32) {
                float x = p[c];
                if (x > v) { v = x; idx = c; }
            }
            warp_argmax_reduce(v, idx);
            if (lane == 0) accum_bin(slice, v, idx, labels, row, lab64);
        }
    }

    __syncthreads();

    int t = threadIdx.x;
    if (t < 30) {
        float s = 0.0f;
        #pragma unroll
        for (int w = 0; w < 8; w++) s += sb[w][t];
        atomicAdd(&g_bins[t], (double)s);
    }
}

__global__ void ece_final_kernel(float* __restrict__ out, int N) {
    if (threadIdx.x == 0 && blockIdx.x == 0) {
        double ece = 0.0;
        double n = (double)N;
        #pragma unroll
        for (int b = 0; b < 10; b++) {
            double cnt = g_bins[b * 3 + 0];
            double sc  = g_bins[b * 3 + 1];
            double sa  = g_bins[b * 3 + 2];
            if (cnt > 0.0) ece += fabs(sc / cnt - sa / cnt) * (cnt / n);
        }
        out[0] = (float)ece;
    }
}

extern "C" void kernel_launch(void* const* d_in, const int* in_sizes, int n_in,
                              void* d_out, int out_size)
{
    // Logits is the (much) larger buffer.
    int li = 0, bi = 1;
    if (in_sizes[1] > in_sizes[0]) { li = 1; bi = 0; }

    const float* logits = (const float*)d_in[li];
    const void*  labels = d_in[bi];

    int N = in_sizes[bi];
    int C = in_sizes[li] / N;

    setup_kernel<<<1, 128>>>(labels, N, C);

    int blocks = 2368;                            // 2 waves at 8 blocks/SM
    long long maxBlocks = ((long long)N + 31) / 32;  // 8 warps x 4 rows
    if (blocks > maxBlocks) blocks = (int)maxBlocks;
    if (blocks < 1) blocks = 1;

    ece_main_kernel<<<blocks, 256>>>(logits, labels, N, C);
    ece_final_kernel<<<1, 32>>>((float*)d_out, N);
}

// round 4
// speedup vs baseline: 2.0526x; 1.2562x over previous
#include <cuda_runtime.h>
#include <math.h>

#define MAXB 4096
// Per-block bin partials: [block][bin*3 + {count,conf,acc}]. Fully
// overwritten by every run -> no zeroing kernel needed.
__device__ float g_part[MAXB * 30];

// Order-preserving float -> uint mapping (total order incl. -INF).
__device__ __forceinline__ unsigned f2ord(float f) {
    unsigned b = __float_as_uint(f);
    return (b & 0x80000000u) ? ~b : (b | 0x80000000u);
}
__device__ __forceinline__ float ord2f(unsigned u) {
    return __uint_as_float((u & 0x80000000u) ? (u ^ 0x80000000u) : ~u);
}

// Warp argmax via redux: max value, min index on ties (first occurrence).
__device__ __forceinline__ void warp_argmax(float v, int idx, float& vout, int& iout) {
    unsigned u  = f2ord(v);
    unsigned um = __reduce_max_sync(0xffffffffu, u);
    unsigned cand = (u == um) ? (unsigned)idx : 0x7fffffffu;
    iout = (int)__reduce_min_sync(0xffffffffu, cand);
    vout = ord2f(um);
}

__device__ __forceinline__ void lane_max4(float4 x, int b, float& v, int& idx) {
    if (x.x > v) { v = x.x; idx = b;     }
    if (x.y > v) { v = x.y; idx = b + 1; }
    if (x.z > v) { v = x.z; idx = b + 2; }
    if (x.w > v) { v = x.w; idx = b + 3; }
}

__device__ __forceinline__ void accum_bin(float* slice, float v, int idx,
                                          const void* labels, int row, int lab64) {
    float conf = __expf(v);
    int bin = (int)ceilf(conf * 10.0f) - 1;
    if (bin >= 0 && bin < 10) {
        int lab;
        if (lab64) lab = (int)((const long long*)labels)[row];
        else       lab = ((const int*)labels)[row];
        slice[bin * 3 + 0] += 1.0f;
        slice[bin * 3 + 1] += conf;
        slice[bin * 3 + 2] += (idx == lab) ? 1.0f : 0.0f;
    }
}

// Warp processes 8 rows per iteration. conf = exp(max(row)); pred = argmax
// (first occurrence); bin = ceil(conf*10)-1, dropped if outside [0,10).
__global__ __launch_bounds__(256) void ece_main_kernel(
    const float* __restrict__ logits,
    const void*  __restrict__ labels,
    int N, int C)
{
    __shared__ float sb[8][30];
    __shared__ int   s_lab64;

    const int warp = threadIdx.x >> 5;
    const int lane = threadIdx.x & 31;

    // Inline label-dtype probe (warp 0): interpret first P entries as int64;
    // any value outside [0,C) proves int32 (random int32 label pairs form
    // values >= 2^32 with overwhelming probability). Deterministic.
    if (warp == 0) {
        const long long* p = (const long long*)labels;
        int P = N / 2; if (P > 256) P = 256;
        bool bad = false;
        for (int i = lane; i < P; i += 32) {
            long long v = p[i];
            if (v < 0 || v >= (long long)C) bad = true;
        }
        unsigned any_bad = __ballot_sync(0xffffffffu, bad);
        if (lane == 0) s_lab64 = any_bad ? 0 : 1;
    }
    if (lane < 30) sb[warp][lane] = 0.0f;
    __syncthreads();

    float* slice = sb[warp];
    const int lab64 = s_lab64;
    const int warpsTotal = gridDim.x * 8;
    const int gwarp = blockIdx.x * 8 + warp;
    const int C4 = C >> 2;

    if ((C & 3) == 0 && C4 <= 32) {
        const bool act = (lane < C4);
        const int b = lane << 2;
        const int nChunks = N >> 3;   // groups of 8 rows
        const float4 NEG = make_float4(-INFINITY, -INFINITY, -INFINITY, -INFINITY);

        for (int ch = gwarp; ch < nChunks; ch += warpsTotal) {
            const int r0 = ch << 3;
            const float4* p = reinterpret_cast<const float4*>(logits + (size_t)r0 * C) + lane;

            // Issue all 8 streaming loads before any reduce (MLP=8/warp).
            float4 x[8];
            #pragma unroll
            for (int r = 0; r < 8; r++)
                x[r] = act ? __ldcs(p + r * C4) : NEG;

            float v[8]; int ix[8];
            #pragma unroll
            for (int r = 0; r < 8; r++) {
                float lv = -INFINITY; int li = 0x7fffffff;
                lane_max4(x[r], b, lv, li);
                warp_argmax(lv, li, v[r], ix[r]);
            }

            if (lane == 0) {
                #pragma unroll
                for (int r = 0; r < 8; r++)
                    accum_bin(slice, v[r], ix[r], labels, r0 + r, lab64);
            }
        }

        // Tail rows (N % 8).
        for (int row = (nChunks << 3) + gwarp; row < N; row += warpsTotal) {
            const float4* p = reinterpret_cast<const float4*>(logits + (size_t)row * C);
            float lv = -INFINITY; int li = 0x7fffffff;
            if (act) { float4 xx = __ldcs(p + lane); lane_max4(xx, b, lv, li); }
            float vv; int ii;
            warp_argmax(lv, li, vv, ii);
            if (lane == 0) accum_bin(slice, vv, ii, labels, row, lab64);
        }
    } else {
        // Generic fallback.
        for (int row = gwarp; row < N; row += warpsTotal) {
            float lv = -INFINITY; int li = 0x7fffffff;
            const float* p = logits + (size_t)row * C;
            for (int c = lane; c < C; c += 32) {
                float xx = p[c];
                if (xx > lv) { lv = xx; li = c; }
            }
            float vv; int ii;
            warp_argmax(lv, li, vv, ii);
            if (lane == 0) accum_bin(slice, vv, ii, labels, row, lab64);
        }
    }

    __syncthreads();

    // Block reduce 8 warp slices -> per-block partials (no atomics).
    int t = threadIdx.x;
    if (t < 30) {
        float s = 0.0f;
        #pragma unroll
        for (int w = 0; w < 8; w++) s += sb[w][t];
        g_part[blockIdx.x * 30 + t] = s;
    }
}

// Reduce per-block partials: warp w handles bin-component w (30 warps).
__global__ __launch_bounds__(960) void ece_final_kernel(
    float* __restrict__ out, int N, int nblocks)
{
    __shared__ double sbins[30];
    const int warp = threadIdx.x >> 5;
    const int lane = threadIdx.x & 31;

    double s = 0.0;
    for (int i = lane; i < nblocks; i += 32)
        s += (double)g_part[i * 30 + warp];
    #pragma unroll
    for (int off = 16; off; off >>= 1)
        s += __shfl_down_sync(0xffffffffu, s, off);
    if (lane == 0) sbins[warp] = s;
    __syncthreads();

    if (threadIdx.x == 0) {
        double ece = 0.0, n = (double)N;
        #pragma unroll
        for (int b = 0; b < 10; b++) {
            double cnt = sbins[b * 3 + 0];
            double sc  = sbins[b * 3 + 1];
            double sa  = sbins[b * 3 + 2];
            if (cnt > 0.0) ece += fabs(sc / cnt - sa / cnt) * (cnt / n);
        }
        out[0] = (float)ece;
    }
}

extern "C" void kernel_launch(void* const* d_in, const int* in_sizes, int n_in,
                              void* d_out, int out_size)
{
    // Logits is the (much) larger buffer.
    int li = 0, bi = 1;
    if (in_sizes[1] > in_sizes[0]) { li = 1; bi = 0; }

    const float* logits = (const float*)d_in[li];
    const void*  labels = d_in[bi];

    int N = in_sizes[bi];
    int C = in_sizes[li] / N;

    int blocks = 1216;                               // 8 blocks/SM target
    long long maxBlocks = ((long long)N + 63) / 64;  // 8 warps x 8 rows
    if (blocks > maxBlocks) blocks = (int)maxBlocks;
    if (blocks < 1) blocks = 1;
    if (blocks > MAXB) blocks = MAXB;

    ece_main_kernel<<<blocks, 256>>>(logits, labels, N, C);
    ece_final_kernel<<<1, 960>>>((float*)d_out, N, blocks);
}